// round 4
// baseline (speedup 1.0000x reference)
#include <cuda_runtime.h>
#include <cuda_bf16.h>

// ---------------------------------------------------------------------------
// Fused SSIM loss:
//   result = 1 - (mean(ssim_map(f,s1)) + mean(ssim_map(f,s2))) / 2
// 11x11 Gaussian blur (sigma=1.5) is separable: vertical pass in registers,
// horizontal pass from shared memory with a sliding register window.
// ---------------------------------------------------------------------------

#define IMG_W 512
#define IMG_H 512
#define N_PLANES 48               // B*C = 16*3
#define OUT_TW 54                 // output tile width
#define OUT_TH 32                 // output tile height
#define IN_TW 64                  // OUT_TW + 10 halo
#define VB_STRIDE 65              // padded row stride of v-buffer (banks)
#define VB_FLOATS (8 * 32 * VB_STRIDE + 32)   // +32 slack for overread
#define SMEM_BYTES (VB_FLOATS * 4)

// Gaussian taps, sigma=1.5, normalized (compile-time literals so ptxas emits
// FFMA with immediate multiplier: rt 1/SMSP instead of 2).
__device__ constexpr float GW[11] = {
    0.00102838f, 0.00759874f, 0.03600077f, 0.10936055f, 0.21300554f,
    0.26601173f,
    0.21300554f, 0.10936055f, 0.03600077f, 0.00759874f, 0.00102838f
};

__device__ double g_ssim_accum;

__global__ void ssim_init_kernel() { g_ssim_accum = 0.0; }

__global__ void ssim_final_kernel(float* out) {
    const double npix = (double)N_PLANES * IMG_H * IMG_W;
    out[0] = (float)(1.0 - g_ssim_accum / (2.0 * npix));
}

extern "C" __global__ void __launch_bounds__(256, 2)
ssim_fused_kernel(const float* __restrict__ F,
                  const float* __restrict__ S1,
                  const float* __restrict__ S2) {
    extern __shared__ float vbuf[];   // [8 ch][32 rows][VB_STRIDE]

    const int tid = threadIdx.x;
    const int x0 = blockIdx.x * OUT_TW;
    const int y0 = blockIdx.y * OUT_TH;
    const int plane = blockIdx.z;
    const float* __restrict__ Fp  = F  + (size_t)plane * (IMG_H * IMG_W);
    const float* __restrict__ S1p = S1 + (size_t)plane * (IMG_H * IMG_W);
    const float* __restrict__ S2p = S2 + (size_t)plane * (IMG_H * IMG_W);

    // ---------------- Phase A: vertical blur, register-resident -------------
    {
        const int col   = tid & 63;        // 0..63 input column of tile
        const int chunk = tid >> 6;        // 0..3  -> v-rows [chunk*8, +8)
        const int xg = x0 - 5 + col;
        const bool colok = ((unsigned)xg < (unsigned)IMG_W);
        const int rbase = y0 + chunk * 8 - 5;

        float acc[8][8];                   // [out-row j][channel]
        #pragma unroll
        for (int j = 0; j < 8; ++j)
            #pragma unroll
            for (int c = 0; c < 8; ++c) acc[j][c] = 0.0f;

        #pragma unroll
        for (int r = 0; r < 18; ++r) {
            const int ry = rbase + r;
            float f = 0.0f, a = 0.0f, b = 0.0f;
            if (colok && (unsigned)ry < (unsigned)IMG_H) {
                const int idx = ry * IMG_W + xg;
                f = Fp[idx]; a = S1p[idx]; b = S2p[idx];
            }
            const float p3 = f * f, p4 = a * a, p5 = b * b;
            const float p6 = f * a, p7 = f * b;
            // input row r feeds out rows j in [r-10, r] clipped to [0,7],
            // with tap GW[r-j]. All indices compile-time after unroll.
            const int jlo = (r - 10) > 0 ? (r - 10) : 0;
            const int jhi = r < 7 ? r : 7;
            #pragma unroll
            for (int j = jlo; j <= jhi; ++j) {
                const float w = GW[r - j];
                acc[j][0] += w * f;   acc[j][1] += w * a;
                acc[j][2] += w * b;   acc[j][3] += w * p3;
                acc[j][4] += w * p4;  acc[j][5] += w * p5;
                acc[j][6] += w * p6;  acc[j][7] += w * p7;
            }
        }

        #pragma unroll
        for (int j = 0; j < 8; ++j) {
            const int vr = chunk * 8 + j;
            #pragma unroll
            for (int c = 0; c < 8; ++c)
                vbuf[(c * 32 + vr) * VB_STRIDE + col] = acc[j][c];
        }
    }
    __syncthreads();

    // ---------------- Phase B: horizontal blur + SSIM epilogue --------------
    float lsum = 0.0f;
    {
        const int row  = tid >> 3;         // 0..31
        const int slot = tid & 7;          // 0..7 -> 7 outputs each
        const int c0 = slot * 7;           // local out col base (0..49)

        float hb[8][7];
        #pragma unroll
        for (int c = 0; c < 8; ++c) {
            float wnd[17];
            const int base = (c * 32 + row) * VB_STRIDE + c0;
            #pragma unroll
            for (int k = 0; k < 17; ++k) wnd[k] = vbuf[base + k];
            #pragma unroll
            for (int j = 0; j < 7; ++j) {
                float s = GW[0] * wnd[j];
                #pragma unroll
                for (int t = 1; t < 11; ++t) s += GW[t] * wnd[j + t];
                hb[c][j] = s;
            }
        }

        const float C1c = 1e-4f;   // 0.01^2
        const float C2c = 9e-4f;   // 0.03^2
        #pragma unroll
        for (int j = 0; j < 7; ++j) {
            const int lc = c0 + j;
            const int xo = x0 + lc;
            if (lc < OUT_TW && xo < IMG_W) {
                const float mu1 = hb[0][j], mu2 = hb[1][j], mu3 = hb[2][j];
                const float m11 = mu1 * mu1, m22 = mu2 * mu2, m33 = mu3 * mu3;
                const float m12 = mu1 * mu2, m13 = mu1 * mu3;
                const float s11 = hb[3][j] - m11;
                const float s22 = hb[4][j] - m22;
                const float s33 = hb[5][j] - m33;
                const float s12 = hb[6][j] - m12;
                const float s13 = hb[7][j] - m13;
                const float n1 = (2.0f * m12 + C1c) * (2.0f * s12 + C2c);
                const float d1 = (m11 + m22 + C1c) * (s11 + s22 + C2c);
                const float n2 = (2.0f * m13 + C1c) * (2.0f * s13 + C2c);
                const float d2 = (m11 + m33 + C1c) * (s11 + s33 + C2c);
                lsum += __fdividef(n1, d1) + __fdividef(n2, d2);
            }
        }
    }

    // ---------------- block reduction + one double atomic -------------------
    #pragma unroll
    for (int o = 16; o; o >>= 1)
        lsum += __shfl_down_sync(0xffffffffu, lsum, o);
    __shared__ float wsum[8];
    if ((tid & 31) == 0) wsum[tid >> 5] = lsum;
    __syncthreads();
    if (tid < 8) {
        float v = wsum[tid];
        #pragma unroll
        for (int o = 4; o; o >>= 1)
            v += __shfl_down_sync(0x000000ffu, v, o);
        if (tid == 0) atomicAdd(&g_ssim_accum, (double)v);
    }
}

extern "C" void kernel_launch(void* const* d_in, const int* in_sizes, int n_in,
                              void* d_out, int out_size) {
    (void)in_sizes; (void)n_in; (void)out_size;
    const float* F  = (const float*)d_in[0];
    const float* S1 = (const float*)d_in[1];
    const float* S2 = (const float*)d_in[2];
    float* out = (float*)d_out;

    cudaFuncSetAttribute(ssim_fused_kernel,
                         cudaFuncAttributeMaxDynamicSharedMemorySize,
                         SMEM_BYTES);

    ssim_init_kernel<<<1, 1>>>();
    dim3 grid((IMG_W + OUT_TW - 1) / OUT_TW,   // 10
              IMG_H / OUT_TH,                  // 16
              N_PLANES);                       // 48
    ssim_fused_kernel<<<grid, 256, SMEM_BYTES>>>(F, S1, S2);
    ssim_final_kernel<<<1, 1>>>(out);
}